// round 10
// baseline (speedup 1.0000x reference)
#include <cuda_runtime.h>
#include <cuda_bf16.h>
#include <math.h>
#include <stdint.h>

#define BB 512
#define TT 512
#define DD 128
#define HH 64

// Scratch, row-major: g_pre[row=b*TT+t][64], g_ball[row][8]. +8 pad rows for
// the scan's prefetch (pad values loaded but never consumed).
__device__ float g_pre[((size_t)BB * TT + 8) * HH];
__device__ float g_ball[((size_t)BB * TT + 8) * 8];

// ---------------- helpers ----------------
__device__ __forceinline__ uint32_t s2u(const void* p) {
    uint32_t a;
    asm("{ .reg .u64 t; cvta.to.shared.u64 t, %1; cvt.u32.u64 %0, t; }"
        : "=r"(a) : "l"(p));
    return a;
}
__device__ __forceinline__ void ldsm4(uint32_t addr, uint32_t& r0, uint32_t& r1,
                                      uint32_t& r2, uint32_t& r3) {
    asm volatile("ldmatrix.sync.aligned.m8n8.x4.shared.b16 {%0,%1,%2,%3}, [%4];"
                 : "=r"(r0), "=r"(r1), "=r"(r2), "=r"(r3) : "r"(addr));
}
__device__ __forceinline__ void ldsm4t(uint32_t addr, uint32_t& r0, uint32_t& r1,
                                       uint32_t& r2, uint32_t& r3) {
    asm volatile("ldmatrix.sync.aligned.m8n8.x4.trans.shared.b16 {%0,%1,%2,%3}, [%4];"
                 : "=r"(r0), "=r"(r1), "=r"(r2), "=r"(r3) : "r"(addr));
}
__device__ __forceinline__ void ldsm2t(uint32_t addr, uint32_t& r0, uint32_t& r1) {
    asm volatile("ldmatrix.sync.aligned.m8n8.x2.trans.shared.b16 {%0,%1}, [%2];"
                 : "=r"(r0), "=r"(r1) : "r"(addr));
}
__device__ __forceinline__ void mma16816(float* c, uint32_t a0, uint32_t a1,
                                         uint32_t a2, uint32_t a3, uint32_t b0,
                                         uint32_t b1) {
    asm volatile(
        "mma.sync.aligned.m16n8k16.row.col.f32.bf16.bf16.f32 "
        "{%0,%1,%2,%3},{%4,%5,%6,%7},{%8,%9},{%0,%1,%2,%3};"
        : "+f"(c[0]), "+f"(c[1]), "+f"(c[2]), "+f"(c[3])
        : "r"(a0), "r"(a1), "r"(a2), "r"(a3), "r"(b0), "r"(b1));
}
__device__ __forceinline__ void split2(float a, float b, uint32_t& hi, uint32_t& lo) {
    uint32_t h;
    asm("cvt.rn.bf16x2.f32 %0, %1, %2;" : "=r"(h) : "f"(b), "f"(a));
    float ah = __uint_as_float(h << 16);
    float bh = __uint_as_float(h & 0xFFFF0000u);
    float al = a - ah, bl = b - bh;
    uint32_t l;
    asm("cvt.rn.bf16x2.f32 %0, %1, %2;" : "=r"(l) : "f"(bl), "f"(al));
    hi = h;
    lo = l;
}
__device__ __forceinline__ float tanh_fast(float x) {
    float y;
    asm("tanh.approx.f32 %0, %1;" : "=f"(y) : "f"(x));
    return y;
}
__device__ __forceinline__ float gelu_fast(float x) {
    float x2 = x * x;
    float u = x * fmaf(x2, 0.0356774081f, 0.7978845608f);
    float t = tanh_fast(u);
    return x * fmaf(t, 0.5f, 0.5f);
}
__device__ __forceinline__ float sigmoidf_(float v) { return 1.0f / (1.0f + expf(-v)); }

// =====================================================================
// Phase 1 (TC v2): block = 128 token rows, 256 threads (8 warps).
// Full W1 staged once; x double-buffered per 32-K chunk; bf16-split HMMA.
// =====================================================================
#define P1_SMEM_BYTES 80384
#define SA 40  // A plane row stride (elements)
#define SW 72  // W1/h plane stride
#define S2 88  // W2 plane stride

__global__ __launch_bounds__(256, 2) void phase1_kernel(
    const float* __restrict__ x, const float* __restrict__ W1,
    const float* __restrict__ b1, const float* __restrict__ ln_g,
    const float* __restrict__ ln_b, const float* __restrict__ W_inn,
    const float* __restrict__ b_inn, const float* __restrict__ Wc1,
    const float* __restrict__ bc1) {
    extern __shared__ char sm[];
    __nv_bfloat16* aHi = (__nv_bfloat16*)(sm + 0);
    __nv_bfloat16* aLo = (__nv_bfloat16*)(sm + 10240);
    __nv_bfloat16* w1Hi = (__nv_bfloat16*)(sm + 20480);
    __nv_bfloat16* w1Lo = (__nv_bfloat16*)(sm + 38912);
    __nv_bfloat16* hHi = (__nv_bfloat16*)(sm + 0);
    __nv_bfloat16* hLo = (__nv_bfloat16*)(sm + 18432);
    __nv_bfloat16* w2Hi = (__nv_bfloat16*)(sm + 57344);
    __nv_bfloat16* w2Lo = (__nv_bfloat16*)(sm + 68608);
    float* sLng = (float*)(sm + 79872);
    float* sLnb = (float*)(sm + 80128);

    const int tid = threadIdx.x;
    const int lane = tid & 31, warp = tid >> 5;
    const int lm16 = lane & 15, lh16 = lane >> 4;
    const int qr = lane >> 2, qc = (lane & 3) * 2;
    const int row0 = blockIdx.x * 128;

    float4 xr[4];
#pragma unroll
    for (int j = 0; j < 4; j++) {
        int i = tid + j * 256, r = i >> 3, kq = i & 7;
        xr[j] = __ldg(reinterpret_cast<const float4*>(x + (size_t)(row0 + r) * DD) + kq);
    }

    for (int i = tid; i < DD * HH; i += 256) {
        int k = i >> 6, n = i & 63;
        float f = W1[i];
        __nv_bfloat16 h = __float2bfloat16(f);
        __nv_bfloat16 l = __float2bfloat16(f - __bfloat162float(h));
        w1Hi[k * SW + n] = h;
        w1Lo[k * SW + n] = l;
    }

    {
        int k = tid >> 2;
        int nb = (tid & 3) * 18;
#pragma unroll 1
        for (int nn = 0; nn < 18; nn++) {
            int n = nb + nn;
            float f = (n < 64) ? Wc1[(5 + k) * 64 + n]
                               : (n < 69 ? W_inn[k * 5 + (n - 64)] : 0.0f);
            __nv_bfloat16 h = __float2bfloat16(f);
            __nv_bfloat16 l = __float2bfloat16(f - __bfloat162float(h));
            w2Hi[k * S2 + n] = h;
            w2Lo[k * S2 + n] = l;
        }
    }
    if (tid < 64) {
        sLng[tid] = ln_g[tid];
        sLnb[tid] = ln_b[tid];
    }

    float acc[8][4];
#pragma unroll
    for (int t8 = 0; t8 < 8; t8++) {
        int col = t8 * 8 + qc;
        acc[t8][0] = __ldg(b1 + col);
        acc[t8][1] = __ldg(b1 + col + 1);
        acc[t8][2] = acc[t8][0];
        acc[t8][3] = acc[t8][1];
    }

    const uint32_t uaH = s2u(aHi) + 2 * ((warp * 16 + lm16) * SA + 8 * lh16);
    const uint32_t uaL = s2u(aLo) + 2 * ((warp * 16 + lm16) * SA + 8 * lh16);
    const uint32_t uwH = s2u(w1Hi) + 2 * (lm16 * SW + 8 * lh16);
    const uint32_t uwL = s2u(w1Lo) + 2 * (lm16 * SW + 8 * lh16);

#pragma unroll 1
    for (int c = 0; c < 4; c++) {
        __syncthreads();
#pragma unroll
        for (int j = 0; j < 4; j++) {
            int i = tid + j * 256, r = i >> 3, kq = i & 7;
            uint32_t h0, l0, h1, l1;
            split2(xr[j].x, xr[j].y, h0, l0);
            split2(xr[j].z, xr[j].w, h1, l1);
            int e = r * SA + kq * 4;
            *(uint32_t*)&aHi[e] = h0;
            *(uint32_t*)&aHi[e + 2] = h1;
            *(uint32_t*)&aLo[e] = l0;
            *(uint32_t*)&aLo[e + 2] = l1;
        }
        __syncthreads();
        if (c < 3) {
#pragma unroll
            for (int j = 0; j < 4; j++) {
                int i = tid + j * 256, r = i >> 3, kq = i & 7;
                xr[j] = __ldg(reinterpret_cast<const float4*>(
                                  x + (size_t)(row0 + r) * DD + (c + 1) * 32) + kq);
            }
        }
#pragma unroll
        for (int ks = 0; ks < 2; ks++) {
            uint32_t ah0, ah1, ah2, ah3, al0, al1, al2, al3;
            ldsm4(uaH + ks * 32, ah0, ah1, ah2, ah3);
            ldsm4(uaL + ks * 32, al0, al1, al2, al3);
#pragma unroll
            for (int p = 0; p < 4; p++) {
                uint32_t off = (uint32_t)(c * 32 + ks * 16) * SW * 2 + p * 32;
                uint32_t bh0, bh1, bh2, bh3, bl0, bl1, bl2, bl3;
                ldsm4t(uwH + off, bh0, bh1, bh2, bh3);
                ldsm4t(uwL + off, bl0, bl1, bl2, bl3);
                mma16816(acc[2 * p], ah0, ah1, ah2, ah3, bh0, bh1);
                mma16816(acc[2 * p], ah0, ah1, ah2, ah3, bl0, bl1);
                mma16816(acc[2 * p], al0, al1, al2, al3, bh0, bh1);
                mma16816(acc[2 * p + 1], ah0, ah1, ah2, ah3, bh2, bh3);
                mma16816(acc[2 * p + 1], ah0, ah1, ah2, ah3, bl2, bl3);
                mma16816(acc[2 * p + 1], al0, al1, al2, al3, bh2, bh3);
            }
        }
    }

    // ---- LN (quad shuffles) + gelu + split into h planes ----
    float sA = 0.f, qA = 0.f, sB = 0.f, qB = 0.f;
#pragma unroll
    for (int t8 = 0; t8 < 8; t8++) {
        sA += acc[t8][0] + acc[t8][1];
        qA += acc[t8][0] * acc[t8][0] + acc[t8][1] * acc[t8][1];
        sB += acc[t8][2] + acc[t8][3];
        qB += acc[t8][2] * acc[t8][2] + acc[t8][3] * acc[t8][3];
    }
#pragma unroll
    for (int m = 1; m <= 2; m <<= 1) {
        sA += __shfl_xor_sync(0xffffffffu, sA, m);
        qA += __shfl_xor_sync(0xffffffffu, qA, m);
        sB += __shfl_xor_sync(0xffffffffu, sB, m);
        qB += __shfl_xor_sync(0xffffffffu, qB, m);
    }
    float mA = sA * (1.0f / 64), vA = qA * (1.0f / 64) - mA * mA;
    float rA_ = rsqrtf(vA + 1e-5f);
    float mB = sB * (1.0f / 64), vB = qB * (1.0f / 64) - mB * mB;
    float rB_ = rsqrtf(vB + 1e-5f);

    __syncthreads();

    const int rA = warp * 16 + qr, rB = rA + 8;
#pragma unroll
    for (int t8 = 0; t8 < 8; t8++) {
        int col = t8 * 8 + qc;
        float g0 = sLng[col], g1 = sLng[col + 1];
        float bb0 = sLnb[col], bb1 = sLnb[col + 1];
        float vA0 = gelu_fast(fmaf((acc[t8][0] - mA) * rA_, g0, bb0));
        float vA1 = gelu_fast(fmaf((acc[t8][1] - mA) * rA_, g1, bb1));
        float vB0 = gelu_fast(fmaf((acc[t8][2] - mB) * rB_, g0, bb0));
        float vB1 = gelu_fast(fmaf((acc[t8][3] - mB) * rB_, g1, bb1));
        uint32_t h01, l01;
        split2(vA0, vA1, h01, l01);
        *(uint32_t*)&hHi[rA * SW + col] = h01;
        *(uint32_t*)&hLo[rA * SW + col] = l01;
        split2(vB0, vB1, h01, l01);
        *(uint32_t*)&hHi[rB * SW + col] = h01;
        *(uint32_t*)&hLo[rB * SW + col] = l01;
    }
    __syncthreads();

    // ---- GEMM2 ----
    float ac2[9][4];
#pragma unroll
    for (int t8 = 0; t8 < 8; t8++) {
        int col = t8 * 8 + qc;
        ac2[t8][0] = __ldg(bc1 + col);
        ac2[t8][1] = __ldg(bc1 + col + 1);
        ac2[t8][2] = ac2[t8][0];
        ac2[t8][3] = ac2[t8][1];
    }
    ac2[8][0] = (qc < 5) ? __ldg(b_inn + qc) : 0.0f;
    ac2[8][1] = (qc + 1 < 5) ? __ldg(b_inn + qc + 1) : 0.0f;
    ac2[8][2] = ac2[8][0];
    ac2[8][3] = ac2[8][1];

    const uint32_t uhH = s2u(hHi) + 2 * ((warp * 16 + lm16) * SW + 8 * lh16);
    const uint32_t uhL = s2u(hLo) + 2 * ((warp * 16 + lm16) * SW + 8 * lh16);
    const uint32_t u2H = s2u(w2Hi) + 2 * (lm16 * S2 + 8 * lh16);
    const uint32_t u2L = s2u(w2Lo) + 2 * (lm16 * S2 + 8 * lh16);
    const uint32_t u8H = s2u(w2Hi) + 2 * (lm16 * S2 + 64);
    const uint32_t u8L = s2u(w2Lo) + 2 * (lm16 * S2 + 64);

#pragma unroll
    for (int ks = 0; ks < 4; ks++) {
        uint32_t ah0, ah1, ah2, ah3, al0, al1, al2, al3;
        ldsm4(uhH + ks * 32, ah0, ah1, ah2, ah3);
        ldsm4(uhL + ks * 32, al0, al1, al2, al3);
#pragma unroll
        for (int p = 0; p < 4; p++) {
            uint32_t off = ks * (16 * S2 * 2) + p * 32;
            uint32_t bh0, bh1, bh2, bh3, bl0, bl1, bl2, bl3;
            ldsm4t(u2H + off, bh0, bh1, bh2, bh3);
            ldsm4t(u2L + off, bl0, bl1, bl2, bl3);
            mma16816(ac2[2 * p], ah0, ah1, ah2, ah3, bh0, bh1);
            mma16816(ac2[2 * p], ah0, ah1, ah2, ah3, bl0, bl1);
            mma16816(ac2[2 * p], al0, al1, al2, al3, bh0, bh1);
            mma16816(ac2[2 * p + 1], ah0, ah1, ah2, ah3, bh2, bh3);
            mma16816(ac2[2 * p + 1], ah0, ah1, ah2, ah3, bl2, bl3);
            mma16816(ac2[2 * p + 1], al0, al1, al2, al3, bh2, bh3);
        }
        uint32_t b80, b81, c80, c81;
        ldsm2t(u8H + ks * (16 * S2 * 2), b80, b81);
        ldsm2t(u8L + ks * (16 * S2 * 2), c80, c81);
        mma16816(ac2[8], ah0, ah1, ah2, ah3, b80, b81);
        mma16816(ac2[8], ah0, ah1, ah2, ah3, c80, c81);
        mma16816(ac2[8], al0, al1, al2, al3, b80, b81);
    }

    const int growA = row0 + warp * 16 + qr;
#pragma unroll
    for (int t8 = 0; t8 < 8; t8++) {
        int col = t8 * 8 + qc;
        *(float2*)&g_pre[(size_t)growA * 64 + col] = make_float2(ac2[t8][0], ac2[t8][1]);
        *(float2*)&g_pre[(size_t)(growA + 8) * 64 + col] =
            make_float2(ac2[t8][2], ac2[t8][3]);
    }
    *(float2*)&g_ball[(size_t)growA * 8 + qc] = make_float2(ac2[8][0], ac2[8][1]);
    *(float2*)&g_ball[(size_t)(growA + 8) * 8 + qc] = make_float2(ac2[8][2], ac2[8][3]);
}

// =====================================================================
// Phase 2 scan (v7): ONE row per warp, 8 lanes per row (data replicated
// across the 4 lane-groups), 8 j/lane, 3-level f32 shuffle butterfly
// (no REDUX / F2I / I2F on the chain). 512 single-warp CTAs, depth-4
// register prefetch.
// =====================================================================
__global__ __launch_bounds__(32) void scan_kernel(
    const float* __restrict__ Wc1, const float* __restrict__ Wc2,
    const float* __restrict__ bc2, const float* __restrict__ corr_scale,
    const float* __restrict__ raw_aL, const float* __restrict__ raw_aT,
    const float* __restrict__ raw_g, const float* __restrict__ raw_aR,
    const float* __restrict__ omega, float* __restrict__ out) {
    const int lane = threadIdx.x;
    const int row = blockIdx.x;
    const int sub = lane & 7;  // groups of 8 lanes replicate the row
    const int j0 = sub * 8;

    float w1s[5][8], w2[8][5], bc[5];
#pragma unroll
    for (int k = 0; k < 5; k++)
#pragma unroll
        for (int jj = 0; jj < 8; jj++) w1s[k][jj] = __ldg(&Wc1[k * 64 + j0 + jj]);
#pragma unroll
    for (int jj = 0; jj < 8; jj++)
#pragma unroll
        for (int k = 0; k < 5; k++) w2[jj][k] = __ldg(&Wc2[(j0 + jj) * 5 + k]);
#pragma unroll
    for (int k = 0; k < 5; k++) bc[k] = __ldg(bc2 + k);

    const float aL = sigmoidf_(__ldg(raw_aL)) * 0.15f + 0.85f;
    const float aT = sigmoidf_(__ldg(raw_aT)) * 0.25f + 0.70f;
    const float gg = sigmoidf_(__ldg(raw_g)) * 0.20f + 0.80f;
    const float aR = sigmoidf_(__ldg(raw_aR)) * 0.40f;
    const float om = __ldg(omega);
    const float gc = gg * cosf(om), gs = gg * sinf(om), ngs = -gs;
    const float cs = __ldg(corr_scale);

    float s0 = 0.f, s1 = 0.f, s2v = 0.f, s3 = 0.f, s4 = 0.f;

    float pb[4][8];
    float bb[4][5];
#pragma unroll
    for (int u = 0; u < 4; u++) {
        const float* pp = g_pre + ((size_t)row * TT + u) * HH + j0;
        float4 a0 = __ldg(reinterpret_cast<const float4*>(pp));
        float4 a1 = __ldg(reinterpret_cast<const float4*>(pp) + 1);
        pb[u][0] = a0.x; pb[u][1] = a0.y; pb[u][2] = a0.z; pb[u][3] = a0.w;
        pb[u][4] = a1.x; pb[u][5] = a1.y; pb[u][6] = a1.z; pb[u][7] = a1.w;
        const float* bp = g_ball + ((size_t)row * TT + u) * 8;
        float4 c = __ldg(reinterpret_cast<const float4*>(bp));
        bb[u][0] = c.x; bb[u][1] = c.y; bb[u][2] = c.z; bb[u][3] = c.w;
        bb[u][4] = __ldg(bp + 4);
    }

#pragma unroll 1
    for (int tb = 0; tb < TT; tb += 4) {
#pragma unroll
        for (int u = 0; u < 4; u++) {
            const int t = tb + u;
            float sl0 = fmaf(s0, aL, bb[u][0]);
            float sl1 = fmaf(s1, aT, bb[u][1]);
            float sl2 = fmaf(s2v, gc, fmaf(s3, gs, bb[u][2]));
            float sl3 = fmaf(s3, gc, fmaf(s2v, ngs, bb[u][3]));
            float sl4 = fmaf(s4, aR, bb[u][4]);

            // hmlp = gelu(sl @ Wc1_s + pre); partials into two chains
            float pa0 = 0.f, pa1 = 0.f, pa2 = 0.f, pa3 = 0.f, pa4 = 0.f;
            float qb0 = 0.f, qb1 = 0.f, qb2 = 0.f, qb3 = 0.f, qb4 = 0.f;
#pragma unroll
            for (int jj = 0; jj < 8; jj++) {
                float za = fmaf(sl0, w1s[0][jj], pb[u][jj]);
                float zb = sl1 * w1s[1][jj];
                za = fmaf(sl2, w1s[2][jj], za);
                zb = fmaf(sl3, w1s[3][jj], zb);
                za = fmaf(sl4, w1s[4][jj], za);
                float hg = gelu_fast(za + zb);
                if (jj & 1) {
                    qb0 = fmaf(hg, w2[jj][0], qb0);
                    qb1 = fmaf(hg, w2[jj][1], qb1);
                    qb2 = fmaf(hg, w2[jj][2], qb2);
                    qb3 = fmaf(hg, w2[jj][3], qb3);
                    qb4 = fmaf(hg, w2[jj][4], qb4);
                } else {
                    pa0 = fmaf(hg, w2[jj][0], pa0);
                    pa1 = fmaf(hg, w2[jj][1], pa1);
                    pa2 = fmaf(hg, w2[jj][2], pa2);
                    pa3 = fmaf(hg, w2[jj][3], pa3);
                    pa4 = fmaf(hg, w2[jj][4], pa4);
                }
            }
            float p0 = pa0 + qb0, p1 = pa1 + qb1, p2 = pa2 + qb2,
                  p3 = pa3 + qb3, p4 = pa4 + qb4;

            // prefetch t+4 (pad rows make this safe)
            {
                const float* pp = g_pre + ((size_t)row * TT + t + 4) * HH + j0;
                float4 a0 = __ldg(reinterpret_cast<const float4*>(pp));
                float4 a1 = __ldg(reinterpret_cast<const float4*>(pp) + 1);
                pb[u][0] = a0.x; pb[u][1] = a0.y; pb[u][2] = a0.z; pb[u][3] = a0.w;
                pb[u][4] = a1.x; pb[u][5] = a1.y; pb[u][6] = a1.z; pb[u][7] = a1.w;
                const float* bp = g_ball + ((size_t)row * TT + t + 4) * 8;
                float4 c = __ldg(reinterpret_cast<const float4*>(bp));
                bb[u][0] = c.x; bb[u][1] = c.y; bb[u][2] = c.z; bb[u][3] = c.w;
                bb[u][4] = __ldg(bp + 4);
            }

            // 3-level butterfly within each 8-lane group (groups replicate)
#pragma unroll
            for (int m = 1; m <= 4; m <<= 1) {
                p0 += __shfl_xor_sync(0xffffffffu, p0, m);
                p1 += __shfl_xor_sync(0xffffffffu, p1, m);
                p2 += __shfl_xor_sync(0xffffffffu, p2, m);
                p3 += __shfl_xor_sync(0xffffffffu, p3, m);
                p4 += __shfl_xor_sync(0xffffffffu, p4, m);
            }

            s0 = fmaf(cs, tanh_fast(p0 + bc[0]), sl0);
            s1 = fmaf(cs, tanh_fast(p1 + bc[1]), sl1);
            s2v = fmaf(cs, tanh_fast(p2 + bc[2]), sl2);
            s3 = fmaf(cs, tanh_fast(p3 + bc[3]), sl3);
            s4 = fmaf(cs, tanh_fast(p4 + bc[4]), sl4);
        }
    }

    if (lane == 0) {
        out[row * 5 + 0] = s0;
        out[row * 5 + 1] = s1;
        out[row * 5 + 2] = s2v;
        out[row * 5 + 3] = s3;
        out[row * 5 + 4] = s4;
    }
}

// =====================================================================
extern "C" void kernel_launch(void* const* d_in, const int* in_sizes, int n_in,
                              void* d_out, int out_size) {
    const float* x = (const float*)d_in[0];
    const float* W1 = (const float*)d_in[1];
    const float* b1 = (const float*)d_in[2];
    const float* ln_g = (const float*)d_in[3];
    const float* ln_b = (const float*)d_in[4];
    const float* W_inn = (const float*)d_in[5];
    const float* b_inn = (const float*)d_in[6];
    const float* Wc1 = (const float*)d_in[7];
    const float* bc1 = (const float*)d_in[8];
    const float* Wc2 = (const float*)d_in[9];
    const float* bc2 = (const float*)d_in[10];
    const float* corr_scale = (const float*)d_in[11];
    const float* raw_aL = (const float*)d_in[12];
    const float* raw_aT = (const float*)d_in[13];
    const float* raw_g = (const float*)d_in[14];
    const float* raw_aR = (const float*)d_in[15];
    const float* omega = (const float*)d_in[16];
    float* out = (float*)d_out;

    cudaFuncSetAttribute(phase1_kernel, cudaFuncAttributeMaxDynamicSharedMemorySize,
                         P1_SMEM_BYTES);

    phase1_kernel<<<(BB * TT) / 128, 256, P1_SMEM_BYTES>>>(
        x, W1, b1, ln_g, ln_b, W_inn, b_inn, Wc1, bc1);
    scan_kernel<<<BB, 32>>>(Wc1, Wc2, bc2, corr_scale, raw_aL, raw_aT, raw_g,
                            raw_aR, omega, out);
}

// round 11
// speedup vs baseline: 1.4747x; 1.4747x over previous
#include <cuda_runtime.h>
#include <cuda_bf16.h>
#include <math.h>
#include <stdint.h>

#define BB 512
#define TT 512
#define DD 128
#define HH 64

// Scratch, row-major: g_pre[row=b*TT+t][64], g_ball[row][8]. +8 pad rows for
// the scan's prefetch (pad values loaded but never consumed).
__device__ float g_pre[((size_t)BB * TT + 8) * HH];
__device__ float g_ball[((size_t)BB * TT + 8) * 8];

// ---------------- helpers ----------------
__device__ __forceinline__ uint32_t s2u(const void* p) {
    uint32_t a;
    asm("{ .reg .u64 t; cvta.to.shared.u64 t, %1; cvt.u32.u64 %0, t; }"
        : "=r"(a) : "l"(p));
    return a;
}
__device__ __forceinline__ void ldsm4(uint32_t addr, uint32_t& r0, uint32_t& r1,
                                      uint32_t& r2, uint32_t& r3) {
    asm volatile("ldmatrix.sync.aligned.m8n8.x4.shared.b16 {%0,%1,%2,%3}, [%4];"
                 : "=r"(r0), "=r"(r1), "=r"(r2), "=r"(r3) : "r"(addr));
}
__device__ __forceinline__ void ldsm4t(uint32_t addr, uint32_t& r0, uint32_t& r1,
                                       uint32_t& r2, uint32_t& r3) {
    asm volatile("ldmatrix.sync.aligned.m8n8.x4.trans.shared.b16 {%0,%1,%2,%3}, [%4];"
                 : "=r"(r0), "=r"(r1), "=r"(r2), "=r"(r3) : "r"(addr));
}
__device__ __forceinline__ void ldsm2t(uint32_t addr, uint32_t& r0, uint32_t& r1) {
    asm volatile("ldmatrix.sync.aligned.m8n8.x2.trans.shared.b16 {%0,%1}, [%2];"
                 : "=r"(r0), "=r"(r1) : "r"(addr));
}
__device__ __forceinline__ void mma16816(float* c, uint32_t a0, uint32_t a1,
                                         uint32_t a2, uint32_t a3, uint32_t b0,
                                         uint32_t b1) {
    asm volatile(
        "mma.sync.aligned.m16n8k16.row.col.f32.bf16.bf16.f32 "
        "{%0,%1,%2,%3},{%4,%5,%6,%7},{%8,%9},{%0,%1,%2,%3};"
        : "+f"(c[0]), "+f"(c[1]), "+f"(c[2]), "+f"(c[3])
        : "r"(a0), "r"(a1), "r"(a2), "r"(a3), "r"(b0), "r"(b1));
}
__device__ __forceinline__ void split2(float a, float b, uint32_t& hi, uint32_t& lo) {
    uint32_t h;
    asm("cvt.rn.bf16x2.f32 %0, %1, %2;" : "=r"(h) : "f"(b), "f"(a));
    float ah = __uint_as_float(h << 16);
    float bh = __uint_as_float(h & 0xFFFF0000u);
    float al = a - ah, bl = b - bh;
    uint32_t l;
    asm("cvt.rn.bf16x2.f32 %0, %1, %2;" : "=r"(l) : "f"(bl), "f"(al));
    hi = h;
    lo = l;
}
__device__ __forceinline__ float tanh_fast(float x) {
    float y;
    asm("tanh.approx.f32 %0, %1;" : "=f"(y) : "f"(x));
    return y;
}
__device__ __forceinline__ float gelu_fast(float x) {
    float x2 = x * x;
    float u = x * fmaf(x2, 0.0356774081f, 0.7978845608f);
    float t = tanh_fast(u);
    return x * fmaf(t, 0.5f, 0.5f);
}
__device__ __forceinline__ int redux_add_s32(int v) {
    int r;
    asm("redux.sync.add.s32 %0, %1, 0xffffffff;" : "=r"(r) : "r"(v));
    return r;
}
__device__ __forceinline__ float sigmoidf_(float v) { return 1.0f / (1.0f + expf(-v)); }

// =====================================================================
// Phase 1 (TC v3): block = 128 token rows, 256 threads (8 warps).
// Full W1 staged once (VECTORIZED), W2comb staged VECTORIZED; x
// double-buffered per 32-K chunk; bf16-split HMMA.
// =====================================================================
#define P1_SMEM_BYTES 80384
#define SA 40  // A plane row stride (elements)
#define SW 72  // W1/h plane stride
#define S2 88  // W2 plane stride

__global__ __launch_bounds__(256, 2) void phase1_kernel(
    const float* __restrict__ x, const float* __restrict__ W1,
    const float* __restrict__ b1, const float* __restrict__ ln_g,
    const float* __restrict__ ln_b, const float* __restrict__ W_inn,
    const float* __restrict__ b_inn, const float* __restrict__ Wc1,
    const float* __restrict__ bc1) {
    extern __shared__ char sm[];
    __nv_bfloat16* aHi = (__nv_bfloat16*)(sm + 0);
    __nv_bfloat16* aLo = (__nv_bfloat16*)(sm + 10240);
    __nv_bfloat16* w1Hi = (__nv_bfloat16*)(sm + 20480);
    __nv_bfloat16* w1Lo = (__nv_bfloat16*)(sm + 38912);
    __nv_bfloat16* hHi = (__nv_bfloat16*)(sm + 0);
    __nv_bfloat16* hLo = (__nv_bfloat16*)(sm + 18432);
    __nv_bfloat16* w2Hi = (__nv_bfloat16*)(sm + 57344);
    __nv_bfloat16* w2Lo = (__nv_bfloat16*)(sm + 68608);
    float* sLng = (float*)(sm + 79872);
    float* sLnb = (float*)(sm + 80128);

    const int tid = threadIdx.x;
    const int lane = tid & 31, warp = tid >> 5;
    const int lm16 = lane & 15, lh16 = lane >> 4;
    const int qr = lane >> 2, qc = (lane & 3) * 2;
    const int row0 = blockIdx.x * 128;

    // prologue: prefetch x chunk0 into registers
    float4 xr[4];
#pragma unroll
    for (int j = 0; j < 4; j++) {
        int i = tid + j * 256, r = i >> 3, kq = i & 7;
        xr[j] = __ldg(reinterpret_cast<const float4*>(x + (size_t)(row0 + r) * DD) + kq);
    }

    // stage FULL W1 (hi/lo split), vectorized float4 loads (high MLP)
    {
        float4 wv[8];
#pragma unroll
        for (int j = 0; j < 8; j++) wv[j] = __ldg(reinterpret_cast<const float4*>(W1) + tid + j * 256);
#pragma unroll
        for (int j = 0; j < 8; j++) {
            int i = tid + j * 256;        // float4 index: k = i>>4, col = (i&15)*4
            int k = i >> 4, nq = i & 15;
            uint32_t h0, l0, h1, l1;
            split2(wv[j].x, wv[j].y, h0, l0);
            split2(wv[j].z, wv[j].w, h1, l1);
            int e = k * SW + nq * 4;
            *(uint32_t*)&w1Hi[e] = h0;
            *(uint32_t*)&w1Hi[e + 2] = h1;
            *(uint32_t*)&w1Lo[e] = l0;
            *(uint32_t*)&w1Lo[e + 2] = l1;
        }
    }

    // W2comb = [Wc1_h (64x64) | W_inn (64x5) | 0-pad (64x3)], vectorized
    {
        float4 wv[4];
#pragma unroll
        for (int j = 0; j < 4; j++)
            wv[j] = __ldg(reinterpret_cast<const float4*>(Wc1 + 5 * 64) + tid + j * 256);
#pragma unroll
        for (int j = 0; j < 4; j++) {
            int i = tid + j * 256;  // k = i>>4, col = (i&15)*4
            int k = i >> 4, nq = i & 15;
            uint32_t h0, l0, h1, l1;
            split2(wv[j].x, wv[j].y, h0, l0);
            split2(wv[j].z, wv[j].w, h1, l1);
            int e = k * S2 + nq * 4;
            *(uint32_t*)&w2Hi[e] = h0;
            *(uint32_t*)&w2Hi[e + 2] = h1;
            *(uint32_t*)&w2Lo[e] = l0;
            *(uint32_t*)&w2Lo[e + 2] = l1;
        }
    }
    if (tid < 64) {
        float wi[5];
#pragma unroll
        for (int s = 0; s < 5; s++) wi[s] = __ldg(W_inn + tid * 5 + s);
#pragma unroll
        for (int s = 0; s < 5; s++) {
            __nv_bfloat16 h = __float2bfloat16(wi[s]);
            __nv_bfloat16 l = __float2bfloat16(wi[s] - __bfloat162float(h));
            w2Hi[tid * S2 + 64 + s] = h;
            w2Lo[tid * S2 + 64 + s] = l;
        }
#pragma unroll
        for (int s = 5; s < 8; s++) {
            w2Hi[tid * S2 + 64 + s] = __float2bfloat16(0.f);
            w2Lo[tid * S2 + 64 + s] = __float2bfloat16(0.f);
        }
        sLng[tid] = ln_g[tid];
        sLnb[tid] = ln_b[tid];
    }

    // ---- GEMM1 accumulators, init = b1[col] (added pre-LN) ----
    float acc[8][4];
#pragma unroll
    for (int t8 = 0; t8 < 8; t8++) {
        int col = t8 * 8 + qc;
        acc[t8][0] = __ldg(b1 + col);
        acc[t8][1] = __ldg(b1 + col + 1);
        acc[t8][2] = acc[t8][0];
        acc[t8][3] = acc[t8][1];
    }

    const uint32_t uaH = s2u(aHi) + 2 * ((warp * 16 + lm16) * SA + 8 * lh16);
    const uint32_t uaL = s2u(aLo) + 2 * ((warp * 16 + lm16) * SA + 8 * lh16);
    const uint32_t uwH = s2u(w1Hi) + 2 * (lm16 * SW + 8 * lh16);
    const uint32_t uwL = s2u(w1Lo) + 2 * (lm16 * SW + 8 * lh16);

#pragma unroll 1
    for (int c = 0; c < 4; c++) {
        __syncthreads();  // previous chunk's A-plane reads done (covers W1 stage on c=0)
#pragma unroll
        for (int j = 0; j < 4; j++) {
            int i = tid + j * 256, r = i >> 3, kq = i & 7;
            uint32_t h0, l0, h1, l1;
            split2(xr[j].x, xr[j].y, h0, l0);
            split2(xr[j].z, xr[j].w, h1, l1);
            int e = r * SA + kq * 4;
            *(uint32_t*)&aHi[e] = h0;
            *(uint32_t*)&aHi[e + 2] = h1;
            *(uint32_t*)&aLo[e] = l0;
            *(uint32_t*)&aLo[e + 2] = l1;
        }
        __syncthreads();
        if (c < 3) {
#pragma unroll
            for (int j = 0; j < 4; j++) {
                int i = tid + j * 256, r = i >> 3, kq = i & 7;
                xr[j] = __ldg(reinterpret_cast<const float4*>(
                                  x + (size_t)(row0 + r) * DD + (c + 1) * 32) + kq);
            }
        }
#pragma unroll
        for (int ks = 0; ks < 2; ks++) {
            uint32_t ah0, ah1, ah2, ah3, al0, al1, al2, al3;
            ldsm4(uaH + ks * 32, ah0, ah1, ah2, ah3);
            ldsm4(uaL + ks * 32, al0, al1, al2, al3);
#pragma unroll
            for (int p = 0; p < 4; p++) {
                uint32_t off = (uint32_t)(c * 32 + ks * 16) * SW * 2 + p * 32;
                uint32_t bh0, bh1, bh2, bh3, bl0, bl1, bl2, bl3;
                ldsm4t(uwH + off, bh0, bh1, bh2, bh3);
                ldsm4t(uwL + off, bl0, bl1, bl2, bl3);
                mma16816(acc[2 * p], ah0, ah1, ah2, ah3, bh0, bh1);
                mma16816(acc[2 * p], ah0, ah1, ah2, ah3, bl0, bl1);
                mma16816(acc[2 * p], al0, al1, al2, al3, bh0, bh1);
                mma16816(acc[2 * p + 1], ah0, ah1, ah2, ah3, bh2, bh3);
                mma16816(acc[2 * p + 1], ah0, ah1, ah2, ah3, bl2, bl3);
                mma16816(acc[2 * p + 1], al0, al1, al2, al3, bh2, bh3);
            }
        }
    }

    // ---- LN (quad shuffles) + gelu + split into h planes ----
    float sA = 0.f, qA = 0.f, sB = 0.f, qB = 0.f;
#pragma unroll
    for (int t8 = 0; t8 < 8; t8++) {
        sA += acc[t8][0] + acc[t8][1];
        qA += acc[t8][0] * acc[t8][0] + acc[t8][1] * acc[t8][1];
        sB += acc[t8][2] + acc[t8][3];
        qB += acc[t8][2] * acc[t8][2] + acc[t8][3] * acc[t8][3];
    }
#pragma unroll
    for (int m = 1; m <= 2; m <<= 1) {
        sA += __shfl_xor_sync(0xffffffffu, sA, m);
        qA += __shfl_xor_sync(0xffffffffu, qA, m);
        sB += __shfl_xor_sync(0xffffffffu, sB, m);
        qB += __shfl_xor_sync(0xffffffffu, qB, m);
    }
    float mA = sA * (1.0f / 64), vA = qA * (1.0f / 64) - mA * mA;
    float rA_ = rsqrtf(vA + 1e-5f);
    float mB = sB * (1.0f / 64), vB = qB * (1.0f / 64) - mB * mB;
    float rB_ = rsqrtf(vB + 1e-5f);

    __syncthreads();  // all warps done reading A/W1 planes (overlay with h)

    const int rA = warp * 16 + qr, rB = rA + 8;
#pragma unroll
    for (int t8 = 0; t8 < 8; t8++) {
        int col = t8 * 8 + qc;
        float g0 = sLng[col], g1 = sLng[col + 1];
        float bb0 = sLnb[col], bb1 = sLnb[col + 1];
        float vA0 = gelu_fast(fmaf((acc[t8][0] - mA) * rA_, g0, bb0));
        float vA1 = gelu_fast(fmaf((acc[t8][1] - mA) * rA_, g1, bb1));
        float vB0 = gelu_fast(fmaf((acc[t8][2] - mB) * rB_, g0, bb0));
        float vB1 = gelu_fast(fmaf((acc[t8][3] - mB) * rB_, g1, bb1));
        uint32_t h01, l01;
        split2(vA0, vA1, h01, l01);
        *(uint32_t*)&hHi[rA * SW + col] = h01;
        *(uint32_t*)&hLo[rA * SW + col] = l01;
        split2(vB0, vB1, h01, l01);
        *(uint32_t*)&hHi[rB * SW + col] = h01;
        *(uint32_t*)&hLo[rB * SW + col] = l01;
    }
    __syncthreads();

    // ---- GEMM2: [pre | ball] = h @ W2comb + [bc1 | b_inn | 0] ----
    float ac2[9][4];
#pragma unroll
    for (int t8 = 0; t8 < 8; t8++) {
        int col = t8 * 8 + qc;
        ac2[t8][0] = __ldg(bc1 + col);
        ac2[t8][1] = __ldg(bc1 + col + 1);
        ac2[t8][2] = ac2[t8][0];
        ac2[t8][3] = ac2[t8][1];
    }
    ac2[8][0] = (qc < 5) ? __ldg(b_inn + qc) : 0.0f;
    ac2[8][1] = (qc + 1 < 5) ? __ldg(b_inn + qc + 1) : 0.0f;
    ac2[8][2] = ac2[8][0];
    ac2[8][3] = ac2[8][1];

    const uint32_t uhH = s2u(hHi) + 2 * ((warp * 16 + lm16) * SW + 8 * lh16);
    const uint32_t uhL = s2u(hLo) + 2 * ((warp * 16 + lm16) * SW + 8 * lh16);
    const uint32_t u2H = s2u(w2Hi) + 2 * (lm16 * S2 + 8 * lh16);
    const uint32_t u2L = s2u(w2Lo) + 2 * (lm16 * S2 + 8 * lh16);
    const uint32_t u8H = s2u(w2Hi) + 2 * (lm16 * S2 + 64);
    const uint32_t u8L = s2u(w2Lo) + 2 * (lm16 * S2 + 64);

#pragma unroll
    for (int ks = 0; ks < 4; ks++) {
        uint32_t ah0, ah1, ah2, ah3, al0, al1, al2, al3;
        ldsm4(uhH + ks * 32, ah0, ah1, ah2, ah3);
        ldsm4(uhL + ks * 32, al0, al1, al2, al3);
#pragma unroll
        for (int p = 0; p < 4; p++) {
            uint32_t off = ks * (16 * S2 * 2) + p * 32;
            uint32_t bh0, bh1, bh2, bh3, bl0, bl1, bl2, bl3;
            ldsm4t(u2H + off, bh0, bh1, bh2, bh3);
            ldsm4t(u2L + off, bl0, bl1, bl2, bl3);
            mma16816(ac2[2 * p], ah0, ah1, ah2, ah3, bh0, bh1);
            mma16816(ac2[2 * p], ah0, ah1, ah2, ah3, bl0, bl1);
            mma16816(ac2[2 * p], al0, al1, al2, al3, bh0, bh1);
            mma16816(ac2[2 * p + 1], ah0, ah1, ah2, ah3, bh2, bh3);
            mma16816(ac2[2 * p + 1], ah0, ah1, ah2, ah3, bl2, bl3);
            mma16816(ac2[2 * p + 1], al0, al1, al2, al3, bh2, bh3);
        }
        uint32_t b80, b81, c80, c81;
        ldsm2t(u8H + ks * (16 * S2 * 2), b80, b81);
        ldsm2t(u8L + ks * (16 * S2 * 2), c80, c81);
        mma16816(ac2[8], ah0, ah1, ah2, ah3, b80, b81);
        mma16816(ac2[8], ah0, ah1, ah2, ah3, c80, c81);
        mma16816(ac2[8], al0, al1, al2, al3, b80, b81);
    }

    // ---- store pre (rows contiguous 256B) + ball ----
    const int growA = row0 + warp * 16 + qr;
#pragma unroll
    for (int t8 = 0; t8 < 8; t8++) {
        int col = t8 * 8 + qc;
        *(float2*)&g_pre[(size_t)growA * 64 + col] = make_float2(ac2[t8][0], ac2[t8][1]);
        *(float2*)&g_pre[(size_t)(growA + 8) * 64 + col] =
            make_float2(ac2[t8][2], ac2[t8][3]);
    }
    *(float2*)&g_ball[(size_t)growA * 8 + qc] = make_float2(ac2[8][0], ac2[8][1]);
    *(float2*)&g_ball[(size_t)(growA + 8) * 8 + qc] = make_float2(ac2[8][2], ac2[8][3]);
}

// =====================================================================
// Phase 2 scan (v5, PROVEN 90.5us): ONE row per warp, 2 js/lane,
// fixed-point redux.sync.add.s32, depth-8 prefetch. 512 single-warp CTAs.
// =====================================================================
#define FXS 1048576.0f
#define FXSI 9.5367431640625e-7f

__global__ __launch_bounds__(32) void scan_kernel(
    const float* __restrict__ Wc1, const float* __restrict__ Wc2,
    const float* __restrict__ bc2, const float* __restrict__ corr_scale,
    const float* __restrict__ raw_aL, const float* __restrict__ raw_aT,
    const float* __restrict__ raw_g, const float* __restrict__ raw_aR,
    const float* __restrict__ omega, float* __restrict__ out) {
    const int lane = threadIdx.x;
    const int row = blockIdx.x;  // batch index b
    const int j0 = lane * 2;

    float w1s[5][2], w2v[2][5], bc[5];
#pragma unroll
    for (int k = 0; k < 5; k++) {
        w1s[k][0] = __ldg(&Wc1[k * 64 + j0]);
        w1s[k][1] = __ldg(&Wc1[k * 64 + j0 + 1]);
    }
#pragma unroll
    for (int jj = 0; jj < 2; jj++)
#pragma unroll
        for (int k = 0; k < 5; k++) w2v[jj][k] = __ldg(&Wc2[(j0 + jj) * 5 + k]) * FXS;
#pragma unroll
    for (int k = 0; k < 5; k++) bc[k] = __ldg(bc2 + k);

    const float aL = sigmoidf_(__ldg(raw_aL)) * 0.15f + 0.85f;
    const float aT = sigmoidf_(__ldg(raw_aT)) * 0.25f + 0.70f;
    const float gg = sigmoidf_(__ldg(raw_g)) * 0.20f + 0.80f;
    const float aR = sigmoidf_(__ldg(raw_aR)) * 0.40f;
    const float om = __ldg(omega);
    const float gc = gg * cosf(om), gs = gg * sinf(om), ngs = -gs;
    const float cs = __ldg(corr_scale);

    float s0 = 0.f, s1 = 0.f, s2v = 0.f, s3 = 0.f, s4 = 0.f;

    float2 pb[8];
    float bbv[8][5];
#pragma unroll
    for (int u = 0; u < 8; u++) {
        pb[u] = __ldg(reinterpret_cast<const float2*>(
            g_pre + ((size_t)row * TT + u) * HH + j0));
        const float* bp = g_ball + ((size_t)row * TT + u) * 8;
        float4 c = __ldg(reinterpret_cast<const float4*>(bp));
        bbv[u][0] = c.x; bbv[u][1] = c.y; bbv[u][2] = c.z; bbv[u][3] = c.w;
        bbv[u][4] = __ldg(bp + 4);
    }

#pragma unroll 1
    for (int tb = 0; tb < TT; tb += 8) {
#pragma unroll
        for (int u = 0; u < 8; u++) {
            const int t = tb + u;
            float sl0 = fmaf(s0, aL, bbv[u][0]);
            float sl1 = fmaf(s1, aT, bbv[u][1]);
            float sl2 = fmaf(s2v, gc, fmaf(s3, gs, bbv[u][2]));
            float sl3 = fmaf(s3, gc, fmaf(s2v, ngs, bbv[u][3]));
            float sl4 = fmaf(s4, aR, bbv[u][4]);

            float za0 = fmaf(sl0, w1s[0][0], pb[u].x);
            float za1 = fmaf(sl0, w1s[0][1], pb[u].y);
            float zb0 = sl1 * w1s[1][0];
            float zb1 = sl1 * w1s[1][1];
            za0 = fmaf(sl2, w1s[2][0], za0);
            za1 = fmaf(sl2, w1s[2][1], za1);
            zb0 = fmaf(sl3, w1s[3][0], zb0);
            zb1 = fmaf(sl3, w1s[3][1], zb1);
            za0 = fmaf(sl4, w1s[4][0], za0);
            za1 = fmaf(sl4, w1s[4][1], za1);
            float z0 = za0 + zb0;
            float z1 = za1 + zb1;

            float hg0 = gelu_fast(z0);
            float hg1 = gelu_fast(z1);

            float p0 = fmaf(hg0, w2v[0][0], hg1 * w2v[1][0]);
            float p1 = fmaf(hg0, w2v[0][1], hg1 * w2v[1][1]);
            float p2 = fmaf(hg0, w2v[0][2], hg1 * w2v[1][2]);
            float p3 = fmaf(hg0, w2v[0][3], hg1 * w2v[1][3]);
            float p4 = fmaf(hg0, w2v[0][4], hg1 * w2v[1][4]);

            pb[u] = __ldg(reinterpret_cast<const float2*>(
                g_pre + ((size_t)row * TT + t + 8) * HH + j0));
            const float* bp = g_ball + ((size_t)row * TT + t + 8) * 8;
            float4 c = __ldg(reinterpret_cast<const float4*>(bp));
            bbv[u][0] = c.x; bbv[u][1] = c.y; bbv[u][2] = c.z; bbv[u][3] = c.w;
            bbv[u][4] = __ldg(bp + 4);

            int i0 = redux_add_s32(__float2int_rn(p0));
            int i1 = redux_add_s32(__float2int_rn(p1));
            int i2 = redux_add_s32(__float2int_rn(p2));
            int i3 = redux_add_s32(__float2int_rn(p3));
            int i4 = redux_add_s32(__float2int_rn(p4));

            s0 = fmaf(cs, tanh_fast(fmaf(__int2float_rn(i0), FXSI, bc[0])), sl0);
            s1 = fmaf(cs, tanh_fast(fmaf(__int2float_rn(i1), FXSI, bc[1])), sl1);
            s2v = fmaf(cs, tanh_fast(fmaf(__int2float_rn(i2), FXSI, bc[2])), sl2);
            s3 = fmaf(cs, tanh_fast(fmaf(__int2float_rn(i3), FXSI, bc[3])), sl3);
            s4 = fmaf(cs, tanh_fast(fmaf(__int2float_rn(i4), FXSI, bc[4])), sl4);
        }
    }

    if (lane == 0) {
        out[row * 5 + 0] = s0;
        out[row * 5 + 1] = s1;
        out[row * 5 + 2] = s2v;
        out[row * 5 + 3] = s3;
        out[row * 5 + 4] = s4;
    }
}

// =====================================================================
extern "C" void kernel_launch(void* const* d_in, const int* in_sizes, int n_in,
                              void* d_out, int out_size) {
    const float* x = (const float*)d_in[0];
    const float* W1 = (const float*)d_in[1];
    const float* b1 = (const float*)d_in[2];
    const float* ln_g = (const float*)d_in[3];
    const float* ln_b = (const float*)d_in[4];
    const float* W_inn = (const float*)d_in[5];
    const float* b_inn = (const float*)d_in[6];
    const float* Wc1 = (const float*)d_in[7];
    const float* bc1 = (const float*)d_in[8];
    const float* Wc2 = (const float*)d_in[9];
    const float* bc2 = (const float*)d_in[10];
    const float* corr_scale = (const float*)d_in[11];
    const float* raw_aL = (const float*)d_in[12];
    const float* raw_aT = (const float*)d_in[13];
    const float* raw_g = (const float*)d_in[14];
    const float* raw_aR = (const float*)d_in[15];
    const float* omega = (const float*)d_in[16];
    float* out = (float*)d_out;

    cudaFuncSetAttribute(phase1_kernel, cudaFuncAttributeMaxDynamicSharedMemorySize,
                         P1_SMEM_BYTES);

    phase1_kernel<<<(BB * TT) / 128, 256, P1_SMEM_BYTES>>>(
        x, W1, b1, ln_g, ln_b, W_inn, b_inn, Wc1, bc1);
    scan_kernel<<<BB, 32>>>(Wc1, Wc2, bc2, corr_scale, raw_aL, raw_aT, raw_g,
                            raw_aR, omega, out);
}